// round 1
// baseline (speedup 1.0000x reference)
#include <cuda_runtime.h>
#include <math.h>

// Problem constants
#define BB 64
#define NN 64
#define DD 2048
#define NBW 8
#define WW 57
#define SCALE 0.02209708691207961f   // 1/sqrt(2048)
#define LNEPS 1e-5f

// ---------------- scratch (device globals; no runtime allocation) ----------------
__device__ float g_Qn[BB * NN * DD];
__device__ float g_Kn[BB * NN * DD];
__device__ float g_Vn[BB * NN * DD];
__device__ float g_c[BB * WW * NBW];
__device__ float g_h[BB * WW * DD];
__device__ float g_hn[BB * WW * DD];
__device__ float g_q2[BB * WW * DD];
__device__ float g_k2[BB * WW * DD];
__device__ float g_cw2[BB * WW];
__device__ float g_hbar[BB * DD];
__device__ float g_S[BB];

// ---------------- generic SGEMM:  C[M,N] = A[M,K] @ B[N,K]^T + bias[N]*rowScale[row] ----------------
// NT layout: both A and B are row-major with K contiguous.
// Tile 128x128x16, 256 threads, 8x8 per-thread microtile.
__global__ void sgemm_nt(const float* __restrict__ A, const float* __restrict__ B,
                         const float* __restrict__ bias, const float* __restrict__ rowScale,
                         float* __restrict__ C, int M, int N, int K)
{
    __shared__ float As[16][129];
    __shared__ float Bs[16][129];

    const int tid = threadIdx.x;             // 0..255
    const int tx = tid & 15;                 // col group
    const int ty = tid >> 4;                 // row group
    const int rowBase = blockIdx.y * 128;
    const int colBase = blockIdx.x * 128;

    const int lk = tid & 15;                 // k within tile
    const int lm = tid >> 4;                 // row within tile (step 16)

    float acc[8][8];
#pragma unroll
    for (int i = 0; i < 8; i++)
#pragma unroll
        for (int j = 0; j < 8; j++) acc[i][j] = 0.f;

    for (int k0 = 0; k0 < K; k0 += 16) {
        // load A tile (with M guard), transposed into As[k][m]
#pragma unroll
        for (int p = 0; p < 8; p++) {
            int m = lm + p * 16;
            int gr = rowBase + m;
            float v = 0.f;
            if (gr < M) v = A[(size_t)gr * K + k0 + lk];
            As[lk][m] = v;
        }
        // load B tile (N is always a multiple of 128 here)
#pragma unroll
        for (int p = 0; p < 8; p++) {
            int n = lm + p * 16;
            int gn = colBase + n;
            Bs[lk][n] = B[(size_t)gn * K + k0 + lk];
        }
        __syncthreads();

#pragma unroll
        for (int kk = 0; kk < 16; kk++) {
            float ra[8], rb[8];
#pragma unroll
            for (int i = 0; i < 8; i++) ra[i] = As[kk][ty * 8 + i];
#pragma unroll
            for (int j = 0; j < 8; j++) rb[j] = Bs[kk][tx * 8 + j];
#pragma unroll
            for (int i = 0; i < 8; i++)
#pragma unroll
                for (int j = 0; j < 8; j++)
                    acc[i][j] += ra[i] * rb[j];
        }
        __syncthreads();
    }

#pragma unroll
    for (int i = 0; i < 8; i++) {
        int gr = rowBase + ty * 8 + i;
        if (gr >= M) continue;
        float bs = rowScale ? rowScale[gr] : 1.f;
#pragma unroll
        for (int j = 0; j < 8; j++) {
            int gc = colBase + tx * 8 + j;
            C[(size_t)gr * N + gc] = acc[i][j] + bias[gc] * bs;
        }
    }
}

// ---------------- windowed attention: column sums of softmax over 8x8 score tiles ----------------
// grid (WW, BB), 256 threads (8 warps). Warp i computes scores dot[i][0..7], softmaxes its row,
// then atomically accumulates the column sums into shared, written out as c[b][w][j].
__global__ void attn1_kernel(const float* __restrict__ Qn, const float* __restrict__ Kn,
                             float* __restrict__ c)
{
    const int w = blockIdx.x;
    const int b = blockIdx.y;
    const int warp = threadIdx.x >> 5;
    const int lane = threadIdx.x & 31;

    const float* qrow = Qn + ((size_t)b * NN + w + warp) * DD;
    const float* kbase = Kn + ((size_t)b * NN + w) * DD;

    float acc[8];
#pragma unroll
    for (int j = 0; j < 8; j++) acc[j] = 0.f;

    for (int d = lane; d < DD; d += 32) {
        float qv = qrow[d];
#pragma unroll
        for (int j = 0; j < 8; j++)
            acc[j] += qv * kbase[(size_t)j * DD + d];
    }
#pragma unroll
    for (int j = 0; j < 8; j++) {
#pragma unroll
        for (int off = 16; off; off >>= 1)
            acc[j] += __shfl_xor_sync(0xFFFFFFFFu, acc[j], off);
    }

    __shared__ float colsum[8];
    if (threadIdx.x < 8) colsum[threadIdx.x] = 0.f;
    __syncthreads();

    if (lane == 0) {
        float m = -1e30f;
#pragma unroll
        for (int j = 0; j < 8; j++) m = fmaxf(m, acc[j] * SCALE);
        float e[8], s = 0.f;
#pragma unroll
        for (int j = 0; j < 8; j++) { e[j] = __expf(acc[j] * SCALE - m); s += e[j]; }
        float inv = 1.f / s;
#pragma unroll
        for (int j = 0; j < 8; j++) atomicAdd(&colsum[j], e[j] * inv);
    }
    __syncthreads();
    if (threadIdx.x < 8)
        c[((size_t)b * WW + w) * NBW + threadIdx.x] = colsum[threadIdx.x];
}

// ---------------- h = new + nsa  as a dense coefficient matmul ----------------
// h[b,w,d] = sum_n ds_w[w,n]*fc[b,n,d] + sum_n C[b,w,n]*Vn[b,n,d] + ds_b[w]
// where C[b,w,w+j] = c[b,w,j]. grid (DD/128, BB), 128 threads, 57 accumulators/thread.
__global__ void coef_kernel(const float* __restrict__ fc, const float* __restrict__ Vn,
                            const float* __restrict__ c, const float* __restrict__ ds_w,
                            const float* __restrict__ ds_b, float* __restrict__ h)
{
    const int b = blockIdx.y;
    const int d = blockIdx.x * 128 + threadIdx.x;

    __shared__ float sA[WW * NN];
    __shared__ float sB[WW * NN];
    for (int i = threadIdx.x; i < WW * NN; i += 128) { sA[i] = ds_w[i]; sB[i] = 0.f; }
    __syncthreads();
    for (int i = threadIdx.x; i < WW * NBW; i += 128) {
        int w = i / NBW, j = i % NBW;
        sB[w * NN + w + j] = c[((size_t)b * WW + w) * NBW + j];
    }
    __syncthreads();

    const float* fcb = fc + (size_t)b * NN * DD + d;
    const float* vnb = Vn + (size_t)b * NN * DD + d;

    float acc[WW];
#pragma unroll
    for (int w = 0; w < WW; w++) acc[w] = 0.f;

    for (int n = 0; n < NN; n++) {
        float fv = fcb[(size_t)n * DD];
        float vv = vnb[(size_t)n * DD];
#pragma unroll
        for (int w = 0; w < WW; w++)
            acc[w] += fv * sA[w * NN + n] + vv * sB[w * NN + n];
    }

    float* hb = h + (size_t)b * WW * DD + d;
#pragma unroll
    for (int w = 0; w < WW; w++)
        hb[(size_t)w * DD] = acc[w] + ds_b[w];
}

// ---------------- LayerNorm over D per (b,w) row ----------------
__global__ void ln_kernel(const float* __restrict__ h, const float* __restrict__ g,
                          const float* __restrict__ beta, float* __restrict__ hn)
{
    const int row = blockIdx.x;  // b*WW + w
    const int tid = threadIdx.x; // 256
    const float* hr = h + (size_t)row * DD;
    float* outr = hn + (size_t)row * DD;

    float v[8];
    float s = 0.f, s2 = 0.f;
#pragma unroll
    for (int p = 0; p < 8; p++) {
        v[p] = hr[tid + p * 256];
        s += v[p];
        s2 += v[p] * v[p];
    }
#pragma unroll
    for (int off = 16; off; off >>= 1) {
        s += __shfl_xor_sync(0xFFFFFFFFu, s, off);
        s2 += __shfl_xor_sync(0xFFFFFFFFu, s2, off);
    }
    __shared__ float ws[8], ws2[8];
    __shared__ float smu, sinv;
    const int warp = tid >> 5, lane = tid & 31;
    if (lane == 0) { ws[warp] = s; ws2[warp] = s2; }
    __syncthreads();
    if (warp == 0) {
        float a = (lane < 8) ? ws[lane] : 0.f;
        float a2 = (lane < 8) ? ws2[lane] : 0.f;
#pragma unroll
        for (int off = 4; off; off >>= 1) {
            a += __shfl_xor_sync(0xFFFFFFFFu, a, off);
            a2 += __shfl_xor_sync(0xFFFFFFFFu, a2, off);
        }
        if (lane == 0) {
            float mu = a / (float)DD;
            float var = a2 / (float)DD - mu * mu;
            smu = mu;
            sinv = rsqrtf(var + LNEPS);
        }
    }
    __syncthreads();
    float mu = smu, inv = sinv;
#pragma unroll
    for (int p = 0; p < 8; p++) {
        int d = tid + p * 256;
        outr[d] = (v[p] - mu) * inv * g[d] + beta[d];
    }
}

// ---------------- global attention: column sums of softmax over 57x57 scores ----------------
// grid (WW rows i, BB), 256 threads. Accumulates cw2[b][j] via atomics.
__global__ void attn2_kernel(const float* __restrict__ q2, const float* __restrict__ k2,
                             float* __restrict__ cw2)
{
    const int i = blockIdx.x;
    const int b = blockIdx.y;
    const int warp = threadIdx.x >> 5;
    const int lane = threadIdx.x & 31;

    __shared__ float sq[DD];
    __shared__ float sdot[64];
    __shared__ float sm, ss;

    const float* qr = q2 + ((size_t)b * WW + i) * DD;
    for (int d = threadIdx.x; d < DD; d += 256) sq[d] = qr[d];
    __syncthreads();

    for (int j = warp; j < WW; j += 8) {
        const float* kr = k2 + ((size_t)b * WW + j) * DD;
        float a = 0.f;
        for (int d = lane; d < DD; d += 32) a += sq[d] * kr[d];
#pragma unroll
        for (int off = 16; off; off >>= 1)
            a += __shfl_xor_sync(0xFFFFFFFFu, a, off);
        if (lane == 0) sdot[j] = a * SCALE;
    }
    __syncthreads();

    if (threadIdx.x == 0) {
        float m = sdot[0];
        for (int j = 1; j < WW; j++) m = fmaxf(m, sdot[j]);
        float s = 0.f;
        for (int j = 0; j < WW; j++) s += __expf(sdot[j] - m);
        sm = m; ss = s;
    }
    __syncthreads();
    if (threadIdx.x < WW)
        atomicAdd(&cw2[(size_t)b * WW + threadIdx.x],
                  __expf(sdot[threadIdx.x] - sm) / ss);
}

__global__ void zero_kernel(float* __restrict__ p, int n)
{
    int i = blockIdx.x * blockDim.x + threadIdx.x;
    if (i < n) p[i] = 0.f;
}

// ---------------- hbar[b,d] = sum_j cw2[b,j]*hn[b,j,d];  S[b] = sum_j cw2[b,j] ----------------
__global__ void hbar_kernel(const float* __restrict__ hn, const float* __restrict__ cw2,
                            float* __restrict__ hbar, float* __restrict__ S)
{
    const int b = blockIdx.y;
    const int d = blockIdx.x * 256 + threadIdx.x;

    __shared__ float sc[WW];
    if (threadIdx.x < WW) sc[threadIdx.x] = cw2[(size_t)b * WW + threadIdx.x];
    __syncthreads();

    const float* hb = hn + (size_t)b * WW * DD + d;
    float a = 0.f, ssum = 0.f;
#pragma unroll
    for (int j = 0; j < WW; j++) {
        a += sc[j] * hb[(size_t)j * DD];
        ssum += sc[j];
    }
    hbar[(size_t)b * DD + d] = a;
    if (blockIdx.x == 0 && threadIdx.x == 0) S[b] = ssum;
}

// ---------------- launch ----------------
extern "C" void kernel_launch(void* const* d_in, const int* in_sizes, int n_in,
                              void* d_out, int out_size)
{
    (void)in_sizes; (void)n_in; (void)out_size;

    const float* fc     = (const float*)d_in[0];
    const float* nsa_wq = (const float*)d_in[1];
    const float* nsa_bq = (const float*)d_in[2];
    const float* nsa_wk = (const float*)d_in[3];
    const float* nsa_bk = (const float*)d_in[4];
    const float* nsa_wv = (const float*)d_in[5];
    const float* nsa_bv = (const float*)d_in[6];
    const float* ds_w   = (const float*)d_in[7];
    const float* ds_b   = (const float*)d_in[8];
    const float* ln_g   = (const float*)d_in[9];
    const float* ln_b   = (const float*)d_in[10];
    const float* sa_wq  = (const float*)d_in[11];
    const float* sa_bq  = (const float*)d_in[12];
    const float* sa_wk  = (const float*)d_in[13];
    const float* sa_bk  = (const float*)d_in[14];
    const float* sa_wv  = (const float*)d_in[15];
    const float* sa_bv  = (const float*)d_in[16];
    float* out = (float*)d_out;

    float *Qn, *Kn, *Vn, *cbuf, *hbuf, *hnbuf, *q2buf, *k2buf, *cw2buf, *hbarbuf, *Sbuf;
    cudaGetSymbolAddress((void**)&Qn, g_Qn);
    cudaGetSymbolAddress((void**)&Kn, g_Kn);
    cudaGetSymbolAddress((void**)&Vn, g_Vn);
    cudaGetSymbolAddress((void**)&cbuf, g_c);
    cudaGetSymbolAddress((void**)&hbuf, g_h);
    cudaGetSymbolAddress((void**)&hnbuf, g_hn);
    cudaGetSymbolAddress((void**)&q2buf, g_q2);
    cudaGetSymbolAddress((void**)&k2buf, g_k2);
    cudaGetSymbolAddress((void**)&cw2buf, g_cw2);
    cudaGetSymbolAddress((void**)&hbarbuf, g_hbar);
    cudaGetSymbolAddress((void**)&Sbuf, g_S);

    // Stage 1: shared QKV projections over fc_feats (4096 x 2048) @ (2048 x 2048)^T
    sgemm_nt<<<dim3(16, 32), 256>>>(fc, nsa_wq, nsa_bq, nullptr, Qn, BB * NN, DD, DD);
    sgemm_nt<<<dim3(16, 32), 256>>>(fc, nsa_wk, nsa_bk, nullptr, Kn, BB * NN, DD, DD);
    sgemm_nt<<<dim3(16, 32), 256>>>(fc, nsa_wv, nsa_bv, nullptr, Vn, BB * NN, DD, DD);

    // Window attention column sums
    attn1_kernel<<<dim3(WW, BB), 256>>>(Qn, Kn, cbuf);

    // h = downsample + nsa (single coefficient matmul), then LayerNorm
    coef_kernel<<<dim3(DD / 128, BB), 128>>>(fc, Vn, cbuf, ds_w, ds_b, hbuf);
    ln_kernel<<<BB * WW, 256>>>(hbuf, ln_g, ln_b, hnbuf);

    // Stage 2: q2/k2 projections (3648 x 2048) @ (2048 x 2048)^T
    sgemm_nt<<<dim3(16, 29), 256>>>(hnbuf, sa_wq, sa_bq, nullptr, q2buf, BB * WW, DD, DD);
    sgemm_nt<<<dim3(16, 29), 256>>>(hnbuf, sa_wk, sa_bk, nullptr, k2buf, BB * WW, DD, DD);

    // Global attention column sums
    zero_kernel<<<(BB * WW + 255) / 256, 256>>>(cw2buf, BB * WW);
    attn2_kernel<<<dim3(WW, BB), 256>>>(q2buf, k2buf, cw2buf);

    // hbar = cw2-weighted sum of hn rows; final projection through sa_wv
    hbar_kernel<<<dim3(DD / 256, BB), 256>>>(hnbuf, cw2buf, hbarbuf, Sbuf);
    sgemm_nt<<<dim3(16, 1), 256>>>(hbarbuf, sa_wv, sa_bv, Sbuf, out, BB, DD, DD);
}